// round 5
// baseline (speedup 1.0000x reference)
#include <cuda_runtime.h>
#include <math.h>

#define NBLK 148
#define NTHR 256
#define T_STEPS 64
#define BATCH 512
#define OBS_D 256
#define ACT_D 32
#define HID 1024
#define FEAT 512
#define GATES 3072
#define LOG2PI 1.8378770664093453f

__device__ float g_h[2][BATCH * HID];
__device__ float g_gh[BATCH * GATES];
__device__ float g_o1[BATCH * FEAT];
__device__ float g_r1[BATCH * FEAT];
__device__ float g_o2[BATCH * FEAT];
__device__ float g_r2[BATCH * FEAT];
__device__ float g_om[BATCH * OBS_D];
__device__ float g_sse[2];
__device__ unsigned g_cnt = 0;
__device__ unsigned g_gen = 0;

struct Params {
    const float *obs, *act, *rew;
    const float *wih, *whh, *bih, *bhh;
    const float *ow0, *ob0, *ow1, *ob1, *ow2, *ob2;
    const float *rw0, *rb0, *rw1, *rb1, *rw2, *rb2;
    float *out;
};

__device__ __forceinline__ float eluf(float x) { return x > 0.f ? x : expm1f(x); }
__device__ __forceinline__ float sigmf(float x) { return 1.f / (1.f + expf(-x)); }

// Grid barrier: valid because all 148 CTAs are co-resident (one wave, <= SM count).
__device__ __forceinline__ void grid_sync(unsigned &phase) {
    __threadfence();
    __syncthreads();
    if (threadIdx.x == 0) {
        if (atomicAdd(&g_cnt, 1u) == NBLK - 1u) {
            g_cnt = 0u;
            __threadfence();
            *(volatile unsigned *)&g_gen = phase + 1u;
        } else {
            while (*(volatile unsigned *)&g_gen == phase) __nanosleep(64);
        }
    }
    __syncthreads();
    phase += 1u;
}

// acc += A[m0:,k] @ W[n0:,k]^T. A via L2 (.cg, cross-CTA mutable), W via L1.
template <int BM, int BN, int TM, int TN>
__device__ __forceinline__ void gemm_tile(float *acc,
    const float *__restrict__ A, int lda,
    const float *__restrict__ W, int ldw,
    int m0, int n0, int K, float *sA, float *sW)
{
    const int tid = threadIdx.x, tx = tid & 15, ty = tid >> 4;
    for (int k0 = 0; k0 < K; k0 += 16) {
        for (int p = tid; p < BM * 4; p += NTHR) {
            int r = p >> 2, c4 = (p & 3) << 2;
            float4 v = __ldcg((const float4 *)(A + (size_t)(m0 + r) * lda + k0 + c4));
            float *d = sA + r * 17 + c4;
            d[0] = v.x; d[1] = v.y; d[2] = v.z; d[3] = v.w;
        }
        for (int p = tid; p < BN * 4; p += NTHR) {
            int r = p >> 2, c4 = (p & 3) << 2;
            float4 v = *(const float4 *)(W + (size_t)(n0 + r) * ldw + k0 + c4);
            float *d = sW + r * 17 + c4;
            d[0] = v.x; d[1] = v.y; d[2] = v.z; d[3] = v.w;
        }
        __syncthreads();
        #pragma unroll
        for (int k = 0; k < 16; k++) {
            float a[TM], b[TN];
            #pragma unroll
            for (int i = 0; i < TM; i++) a[i] = sA[(ty + (i << 4)) * 17 + k];
            #pragma unroll
            for (int j = 0; j < TN; j++) b[j] = sW[(tx + (j << 4)) * 17 + k];
            #pragma unroll
            for (int i = 0; i < TM; i++)
                #pragma unroll
                for (int j = 0; j < TN; j++)
                    acc[i * TN + j] = fmaf(a[i], b[j], acc[i * TN + j]);
        }
        __syncthreads();
    }
}

// Stage D: gi = [x_obs|act] @ Wih^T (3 gates, 64x64 tile) + fused GRU pointwise.
__device__ void stage_d(const Params &P, int t, bool init,
                        const float *hR, float *hW, float *sA, float *sW, int tile)
{
    const int tid = threadIdx.x, tx = tid & 15, ty = tid >> 4;
    const int m0 = (tile >> 4) << 6, j0 = (tile & 15) << 6;
    float aR[16], aZ[16], aN[16];
    #pragma unroll
    for (int i = 0; i < 16; i++) { aR[i] = 0.f; aZ[i] = 0.f; aN[i] = 0.f; }

    for (int k0 = 0; k0 < 288; k0 += 16) {
        {
            int r = tid >> 2, c4 = (tid & 3) << 2, col = k0 + c4;
            float4 v;
            if (col < 256)
                v = init ? *(const float4 *)(P.obs + (size_t)(m0 + r) * OBS_D + col)
                         : __ldcg((const float4 *)(g_om + (size_t)(m0 + r) * OBS_D + col));
            else if (init) v = make_float4(0.f, 0.f, 0.f, 0.f);
            else v = *(const float4 *)(P.act + (size_t)t * BATCH * ACT_D +
                                       (size_t)(m0 + r) * ACT_D + (col - 256));
            float *d = sA + r * 17 + c4;
            d[0] = v.x; d[1] = v.y; d[2] = v.z; d[3] = v.w;
        }
        for (int p = tid; p < 768; p += NTHR) {
            int g = p >> 8, q = p & 255, r = q >> 2, c4 = (q & 3) << 2;
            float4 v = *(const float4 *)(P.wih + (size_t)(g * HID + j0 + r) * 288 + k0 + c4);
            float *d = sW + g * 1088 + r * 17 + c4;
            d[0] = v.x; d[1] = v.y; d[2] = v.z; d[3] = v.w;
        }
        __syncthreads();
        #pragma unroll
        for (int k = 0; k < 16; k++) {
            float a[4], br[4], bz[4], bn[4];
            #pragma unroll
            for (int i = 0; i < 4; i++) a[i] = sA[(ty + (i << 4)) * 17 + k];
            #pragma unroll
            for (int j = 0; j < 4; j++) {
                int o = (tx + (j << 4)) * 17 + k;
                br[j] = sW[o]; bz[j] = sW[1088 + o]; bn[j] = sW[2176 + o];
            }
            #pragma unroll
            for (int i = 0; i < 4; i++)
                #pragma unroll
                for (int j = 0; j < 4; j++) {
                    aR[i * 4 + j] = fmaf(a[i], br[j], aR[i * 4 + j]);
                    aZ[i * 4 + j] = fmaf(a[i], bz[j], aZ[i * 4 + j]);
                    aN[i * 4 + j] = fmaf(a[i], bn[j], aN[i * 4 + j]);
                }
        }
        __syncthreads();
    }

    #pragma unroll
    for (int i = 0; i < 4; i++) {
        int b = m0 + ty + (i << 4);
        #pragma unroll
        for (int j = 0; j < 4; j++) {
            int jg = j0 + tx + (j << 4);
            float gir = aR[i * 4 + j] + __ldg(P.bih + jg);
            float giz = aZ[i * 4 + j] + __ldg(P.bih + HID + jg);
            float gin = aN[i * 4 + j] + __ldg(P.bih + 2 * HID + jg);
            float ghr, ghz, ghn, hp;
            if (init) {
                ghr = __ldg(P.bhh + jg); ghz = __ldg(P.bhh + HID + jg);
                ghn = __ldg(P.bhh + 2 * HID + jg); hp = 0.f;
            } else {
                const float *g = g_gh + (size_t)b * GATES + jg;
                ghr = __ldcg(g); ghz = __ldcg(g + HID); ghn = __ldcg(g + 2 * HID);
                hp = __ldcg(hR + (size_t)b * HID + jg);
            }
            float rr = sigmf(gir + ghr);
            float zz = sigmf(giz + ghz);
            float nn = tanhf(gin + rr * ghn);
            hW[(size_t)b * HID + jg] = (1.f - zz) * nn + zz * hp;
        }
    }
}

__global__ void __launch_bounds__(NTHR, 1) wm_kernel(Params P)
{
    __shared__ float smem[4352];
    const int tid = threadIdx.x, tx = tid & 15, ty = tid >> 4;
    unsigned phase = *(volatile unsigned *)&g_gen;
    if (blockIdx.x == 0 && tid == 0) { g_sse[0] = 0.f; g_sse[1] = 0.f; }
    float lpo = 0.f, lpr = 0.f;

    for (int tile = blockIdx.x; tile < 128; tile += NBLK)
        stage_d(P, 0, true, nullptr, g_h[0], smem, smem + 1088, tile);
    grid_sync(phase);

    for (int t = 0; t < T_STEPS; t++) {
        const float *hR = g_h[t & 1];
        float *hW = g_h[(t + 1) & 1];

        // A: gh = h@Whh^T+bhh ; o1/r1 = elu(h@W0^T+b0). K=1024.
        for (int tile = blockIdx.x; tile < 256; tile += NBLK) {
            int mt = tile >> 6, nt = tile & 63, m0 = mt << 7;
            const float *W, *bias; float *out; int ldo, n0; bool act;
            if (nt < 48)      { W = P.whh; bias = P.bhh; out = g_gh; ldo = GATES; n0 = nt << 6; act = false; }
            else if (nt < 56) { W = P.ow0; bias = P.ob0; out = g_o1; ldo = FEAT; n0 = (nt - 48) << 6; act = true; }
            else              { W = P.rw0; bias = P.rb0; out = g_r1; ldo = FEAT; n0 = (nt - 56) << 6; act = true; }
            float acc[32];
            #pragma unroll
            for (int i = 0; i < 32; i++) acc[i] = 0.f;
            gemm_tile<128, 64, 8, 4>(acc, hR, HID, W, HID, m0, n0, HID, smem, smem + 2176);
            #pragma unroll
            for (int i = 0; i < 8; i++) {
                int b = m0 + ty + (i << 4);
                #pragma unroll
                for (int j = 0; j < 4; j++) {
                    int n = n0 + tx + (j << 4);
                    float v = acc[i * 4 + j] + __ldg(bias + n);
                    out[(size_t)b * ldo + n] = act ? eluf(v) : v;
                }
            }
        }
        grid_sync(phase);

        // B: o2/r2 = elu(x@W1^T+b1). K=512.
        for (int tile = blockIdx.x; tile < 128; tile += NBLK) {
            int m0 = (tile >> 4) << 6, nt = tile & 15;
            const float *A, *W, *bias; float *out; int n0;
            if (nt < 8) { A = g_o1; W = P.ow1; bias = P.ob1; out = g_o2; n0 = nt << 6; }
            else        { A = g_r1; W = P.rw1; bias = P.rb1; out = g_r2; n0 = (nt - 8) << 6; }
            float acc[16];
            #pragma unroll
            for (int i = 0; i < 16; i++) acc[i] = 0.f;
            gemm_tile<64, 64, 4, 4>(acc, A, FEAT, W, FEAT, m0, n0, FEAT, smem, smem + 1088);
            #pragma unroll
            for (int i = 0; i < 4; i++) {
                int b = m0 + ty + (i << 4);
                #pragma unroll
                for (int j = 0; j < 4; j++) {
                    int n = n0 + tx + (j << 4);
                    out[(size_t)b * FEAT + n] = eluf(acc[i * 4 + j] + __ldg(bias + n));
                }
            }
        }
        grid_sync(phase);

        // C: obs_mean = o2@W2o^T+b (+SSE, store pre_obs) ; rew GEMV (+SSE).
        for (int tile = blockIdx.x; tile < 72; tile += NBLK) {
            if (tile < 64) {
                int m0 = (tile >> 3) << 6, n0 = (tile & 7) << 5;
                float acc[8];
                #pragma unroll
                for (int i = 0; i < 8; i++) acc[i] = 0.f;
                gemm_tile<64, 32, 4, 2>(acc, g_o2, FEAT, P.ow2, FEAT, m0, n0, FEAT, smem, smem + 1088);
                #pragma unroll
                for (int i = 0; i < 4; i++) {
                    int b = m0 + ty + (i << 4);
                    #pragma unroll
                    for (int j = 0; j < 2; j++) {
                        int n = n0 + tx + (j << 4);
                        float mean = acc[i * 2 + j] + __ldg(P.ob2 + n);
                        size_t off = (size_t)t * BATCH * OBS_D + (size_t)b * OBS_D + n;
                        g_om[(size_t)b * OBS_D + n] = mean;
                        P.out[1 + off] = mean;
                        float d = __ldg(P.obs + off) - mean;
                        lpo += d * d;
                    }
                }
            } else {
                int b = ((tile - 64) << 6) + (tid >> 2), seg = tid & 3;
                const float4 *r4 = (const float4 *)(g_r2 + (size_t)b * FEAT + seg * 128);
                const float4 *w4 = (const float4 *)(P.rw2 + seg * 128);
                float s = 0.f;
                #pragma unroll
                for (int k = 0; k < 32; k++) {
                    float4 rv = __ldcg(r4 + k); float4 wv = w4[k];
                    s += rv.x * wv.x + rv.y * wv.y + rv.z * wv.z + rv.w * wv.w;
                }
                s += __shfl_xor_sync(0xffffffffu, s, 1);
                s += __shfl_xor_sync(0xffffffffu, s, 2);
                if (seg == 0) {
                    float mean = s + __ldg(P.rb2);
                    P.out[1 + (size_t)T_STEPS * BATCH * OBS_D + (size_t)t * BATCH + b] = mean;
                    float d = __ldg(P.rew + (size_t)t * BATCH + b) - mean;
                    lpr += d * d;
                }
            }
        }
        grid_sync(phase);

        // D: gi + GRU pointwise -> h_next
        for (int tile = blockIdx.x; tile < 128; tile += NBLK)
            stage_d(P, t, false, hR, hW, smem, smem + 1088, tile);
        grid_sync(phase);
    }

    // loss reduction
    #pragma unroll
    for (int o = 16; o; o >>= 1) {
        lpo += __shfl_xor_sync(0xffffffffu, lpo, o);
        lpr += __shfl_xor_sync(0xffffffffu, lpr, o);
    }
    __syncthreads();
    if ((tid & 31) == 0) { smem[tid >> 5] = lpo; smem[8 + (tid >> 5)] = lpr; }
    __syncthreads();
    if (tid == 0) {
        float a = 0.f, b = 0.f;
        for (int w = 0; w < 8; w++) { a += smem[w]; b += smem[8 + w]; }
        atomicAdd(&g_sse[0], a);
        atomicAdd(&g_sse[1], b);
    }
    grid_sync(phase);
    if (blockIdx.x == 0 && tid == 0) {
        float inv = 1.f / (float)(T_STEPS * BATCH);
        P.out[0] = 0.5f * (g_sse[0] + g_sse[1]) * inv + 0.5f * (OBS_D + 1) * LOG2PI;
    }
}

extern "C" void kernel_launch(void* const* d_in, const int* in_sizes, int n_in,
                              void* d_out, int out_size) {
    Params P;
    P.obs = (const float *)d_in[0];
    P.act = (const float *)d_in[1];
    P.rew = (const float *)d_in[2];
    P.wih = (const float *)d_in[3];
    P.whh = (const float *)d_in[4];
    P.bih = (const float *)d_in[5];
    P.bhh = (const float *)d_in[6];
    P.ow0 = (const float *)d_in[7];
    P.ob0 = (const float *)d_in[8];
    P.ow1 = (const float *)d_in[9];
    P.ob1 = (const float *)d_in[10];
    P.ow2 = (const float *)d_in[11];
    P.ob2 = (const float *)d_in[12];
    P.rw0 = (const float *)d_in[13];
    P.rb0 = (const float *)d_in[14];
    P.rw1 = (const float *)d_in[15];
    P.rb1 = (const float *)d_in[16];
    P.rw2 = (const float *)d_in[17];
    P.rb2 = (const float *)d_in[18];
    P.out = (float *)d_out;
    wm_kernel<<<NBLK, NTHR>>>(P);
}

// round 12
// speedup vs baseline: 2.1999x; 2.1999x over previous
#include <cuda_runtime.h>
#include <cuda_bf16.h>
#include <math.h>
#include <stdint.h>

#define NBLK 148
#define NTHR 256
#define T_STEPS 64
#define BATCH 512
#define OBS_D 256
#define ACT_D 32
#define HID 1024
#define FEAT 512
#define GATES 3072
#define LOG2PI 1.8378770664093453f

// bf16 split-plane arena offsets (elements)
#define OFF_WHH 0
#define OFF_WIH 3145728
#define OFF_OW0 4030464
#define OFF_OW1 4554752
#define OFF_OW2 4816896
#define OFF_RW0 4947968
#define OFF_RW1 5472256
#define OFF_OBS0 5734400
#define OFF_ACT 5865472
#define ARENA_N 6914048

// smem (floats): A bufs: buf*5120 (planeH 2560 + planeL 2560); W at 10240:
//   ABC: + buf*5120 (H/L 2560 each); D: + buf*7680 + gate*2560 (H 1280, L 1280)
#define SMEM_DYN 102400

__device__ __align__(16) __nv_bfloat16 g_wh[ARENA_N], g_wl[ARENA_N];
__device__ __align__(16) __nv_bfloat16 g_hh[2][BATCH * HID], g_hl[2][BATCH * HID];
__device__ __align__(16) __nv_bfloat16 g_o1h[BATCH * FEAT], g_o1l[BATCH * FEAT];
__device__ __align__(16) __nv_bfloat16 g_r1h[BATCH * FEAT], g_r1l[BATCH * FEAT];
__device__ __align__(16) __nv_bfloat16 g_o2h[BATCH * FEAT], g_o2l[BATCH * FEAT];
__device__ __align__(16) __nv_bfloat16 g_r2h[BATCH * FEAT], g_r2l[BATCH * FEAT];
__device__ __align__(16) __nv_bfloat16 g_omh[BATCH * OBS_D], g_oml[BATCH * OBS_D];
__device__ __align__(16) float g_gh[BATCH * GATES];
__device__ float g_sse[2];
__device__ unsigned g_cnt = 0;
__device__ unsigned g_gen = 0;

struct Params {
    const float *obs, *act, *rew;
    const float *wih, *whh, *bih, *bhh;
    const float *ow0, *ob0, *ow1, *ob1, *ow2, *ob2;
    const float *rw0, *rb0, *rw1, *rb1, *rw2, *rb2;
    float *out;
};

__device__ __forceinline__ uint32_t smem_u32(const void *p) {
    uint32_t a;
    asm("{ .reg .u64 t; cvta.to.shared.u64 t, %1; cvt.u32.u64 %0, t; }" : "=r"(a) : "l"(p));
    return a;
}
__device__ __forceinline__ void cpa16(uint32_t d, const void *s) {
    asm volatile("cp.async.cg.shared.global [%0], [%1], 16;" :: "r"(d), "l"(s));
}
#define CP_COMMIT asm volatile("cp.async.commit_group;")
#define CP_WAIT1 asm volatile("cp.async.wait_group 1;")
#define CP_WAIT0 asm volatile("cp.async.wait_group 0;")

__device__ __forceinline__ void mmabf(float *c, const uint32_t *a, uint32_t b0, uint32_t b1) {
    asm volatile(
        "mma.sync.aligned.m16n8k16.row.col.f32.bf16.bf16.f32 "
        "{%0,%1,%2,%3}, {%4,%5,%6,%7}, {%8,%9}, {%0,%1,%2,%3};"
        : "+f"(c[0]), "+f"(c[1]), "+f"(c[2]), "+f"(c[3])
        : "r"(a[0]), "r"(a[1]), "r"(a[2]), "r"(a[3]), "r"(b0), "r"(b1));
}

__device__ __forceinline__ float eluf(float x) { return x > 0.f ? x : (__expf(x) - 1.f); }
__device__ __forceinline__ float sigf(float x) { return 1.f / (1.f + __expf(-x)); }
__device__ __forceinline__ float tanhfast(float x) { return 2.f * sigf(2.f * x) - 1.f; }
__device__ __forceinline__ float bf2f(__nv_bfloat16 x) { return __bfloat162float(x); }

__device__ __forceinline__ __nv_bfloat162 split2(float a, float b, __nv_bfloat162 &lo2) {
    __nv_bfloat162 h2;
    h2.x = __float2bfloat16(a); h2.y = __float2bfloat16(b);
    lo2.x = __float2bfloat16(a - bf2f(h2.x));
    lo2.y = __float2bfloat16(b - bf2f(h2.y));
    return h2;
}

__device__ __forceinline__ void grid_sync(unsigned &phase) {
    __threadfence();
    __syncthreads();
    if (threadIdx.x == 0) {
        if (atomicAdd(&g_cnt, 1u) == NBLK - 1u) {
            g_cnt = 0u;
            __threadfence();
            *(volatile unsigned *)&g_gen = phase + 1u;
        } else {
            while (*(volatile unsigned *)&g_gen == phase) __nanosleep(64);
        }
    }
    __syncthreads();
    phase += 1u;
}

// copy ROWS x 32 bf16 (smem row stride 80B) via cp.async
template <int ROWS>
__device__ __forceinline__ void cpa_bf(float *dstf, const __nv_bfloat16 *src, int ld, int row0, int k0) {
    uint32_t dst = smem_u32(dstf);
    int tid = threadIdx.x;
    #pragma unroll
    for (int i = 0; i < ROWS * 4 / NTHR; i++) {
        int p = tid + i * NTHR;
        int r = p >> 2, c = p & 3;
        cpa16(dst + r * 80 + c * 16, src + (size_t)(row0 + r) * ld + k0 + c * 8);
    }
}

// one 32-k chunk, warp tile 64x32: 2 k16-subchunks x 3 split products
__device__ __forceinline__ void chunk_bf(float acc[4][4][4], const uint32_t *sA, const uint32_t *sW) {
    const int lane = threadIdx.x & 31, g = lane >> 2, t4 = lane & 3;
    const int w = threadIdx.x >> 5, wm = w >> 2, wn = w & 3;
    #pragma unroll
    for (int s = 0; s < 2; s++) {
        int w0 = 8 * s + t4, w1 = w0 + 4;
        uint32_t aH[4][4], aL[4][4];
        #pragma unroll
        for (int mt = 0; mt < 4; mt++) {
            int r = (wm * 64 + mt * 16 + g) * 20;
            aH[mt][0] = sA[r + w0]; aH[mt][1] = sA[r + 160 + w0];
            aH[mt][2] = sA[r + w1]; aH[mt][3] = sA[r + 160 + w1];
            aL[mt][0] = sA[2560 + r + w0]; aL[mt][1] = sA[2560 + r + 160 + w0];
            aL[mt][2] = sA[2560 + r + w1]; aL[mt][3] = sA[2560 + r + 160 + w1];
        }
        #pragma unroll
        for (int nt = 0; nt < 4; nt++) {
            int rb = (wn * 32 + nt * 8 + g) * 20;
            uint32_t bH0 = sW[rb + w0], bH1 = sW[rb + w1];
            uint32_t bL0 = sW[2560 + rb + w0], bL1 = sW[2560 + rb + w1];
            #pragma unroll
            for (int mt = 0; mt < 4; mt++) {
                mmabf(acc[mt][nt], aH[mt], bH0, bH1);
                mmabf(acc[mt][nt], aH[mt], bL0, bL1);
                mmabf(acc[mt][nt], aL[mt], bH0, bH1);
            }
        }
    }
}

// C[128,128] = A @ W^T from bf16 split planes, double-buffered cp.async
__device__ void mm_gemm(float acc[4][4][4],
                        const __nv_bfloat16 *Ah, const __nv_bfloat16 *Al, int lda,
                        const __nv_bfloat16 *Wh, const __nv_bfloat16 *Wl, int ldw,
                        int m0, int n0, int K, float *sm) {
    const int NC = K >> 5;
    #define LD_AW(cc, bb) do { \
        cpa_bf<128>(sm + (bb) * 5120, Ah, lda, m0, (cc) << 5); \
        cpa_bf<128>(sm + (bb) * 5120 + 2560, Al, lda, m0, (cc) << 5); \
        cpa_bf<128>(sm + 10240 + (bb) * 5120, Wh, ldw, n0, (cc) << 5); \
        cpa_bf<128>(sm + 10240 + (bb) * 5120 + 2560, Wl, ldw, n0, (cc) << 5); } while (0)
    LD_AW(0, 0); CP_COMMIT;
    for (int c = 0; c < NC; c++) {
        int buf = c & 1;
        if (c + 1 < NC) { LD_AW(c + 1, buf ^ 1); CP_COMMIT; CP_WAIT1; }
        else CP_WAIT0;
        __syncthreads();
        chunk_bf(acc, (const uint32_t *)(sm + buf * 5120),
                 (const uint32_t *)(sm + 10240 + buf * 5120));
        __syncthreads();
    }
    #undef LD_AW
}

__device__ __forceinline__ void epi44_f32(float acc[4][4][4], const float *bias, float *out,
                                          int ldo, int m0, int n0) {
    const int lane = threadIdx.x & 31, g = lane >> 2, t4 = lane & 3;
    const int w = threadIdx.x >> 5, wm = w >> 2, wn = w & 3;
    #pragma unroll
    for (int mt = 0; mt < 4; mt++) {
        int r0 = m0 + wm * 64 + mt * 16 + g;
        #pragma unroll
        for (int nt = 0; nt < 4; nt++) {
            int col = n0 + wn * 32 + nt * 8 + 2 * t4;
            float2 bb = *(const float2 *)(bias + col);
            *(float2 *)(out + (size_t)r0 * ldo + col) =
                make_float2(acc[mt][nt][0] + bb.x, acc[mt][nt][1] + bb.y);
            *(float2 *)(out + (size_t)(r0 + 8) * ldo + col) =
                make_float2(acc[mt][nt][2] + bb.x, acc[mt][nt][3] + bb.y);
        }
    }
}

__device__ __forceinline__ void epi44_bf(float acc[4][4][4], const float *bias,
                                         __nv_bfloat16 *oh, __nv_bfloat16 *ol,
                                         int ldo, int m0, int n0) {
    const int lane = threadIdx.x & 31, g = lane >> 2, t4 = lane & 3;
    const int w = threadIdx.x >> 5, wm = w >> 2, wn = w & 3;
    #pragma unroll
    for (int mt = 0; mt < 4; mt++) {
        int r0 = m0 + wm * 64 + mt * 16 + g;
        #pragma unroll
        for (int nt = 0; nt < 4; nt++) {
            int col = n0 + wn * 32 + nt * 8 + 2 * t4;
            float2 bb = *(const float2 *)(bias + col);
            float v0 = eluf(acc[mt][nt][0] + bb.x), v1 = eluf(acc[mt][nt][1] + bb.y);
            float v2 = eluf(acc[mt][nt][2] + bb.x), v3 = eluf(acc[mt][nt][3] + bb.y);
            __nv_bfloat162 l2, h2 = split2(v0, v1, l2);
            *(__nv_bfloat162 *)(oh + (size_t)r0 * ldo + col) = h2;
            *(__nv_bfloat162 *)(ol + (size_t)r0 * ldo + col) = l2;
            h2 = split2(v2, v3, l2);
            *(__nv_bfloat162 *)(oh + (size_t)(r0 + 8) * ldo + col) = h2;
            *(__nv_bfloat162 *)(ol + (size_t)(r0 + 8) * ldo + col) = l2;
        }
    }
}

// Stage D: gi (3 gates) over K=288 + fused GRU pointwise. bid < 64.
__device__ void stageD(const Params &P, int t, bool init,
                       const __nv_bfloat16 *hhR, const __nv_bfloat16 *hlR,
                       __nv_bfloat16 *hhW, __nv_bfloat16 *hlW, float *sm) {
    const int tid = threadIdx.x, lane = tid & 31, g = lane >> 2, t4 = lane & 3;
    const int w = tid >> 5, wm = w >> 1, wn = w & 1;
    const int bid = blockIdx.x;
    const int m0 = (bid >> 4) << 7, j0 = (bid & 15) << 6;
    float acc[3][2][4][4];
    #pragma unroll
    for (int a = 0; a < 3; a++)
        #pragma unroll
        for (int b = 0; b < 2; b++)
            #pragma unroll
            for (int c = 0; c < 4; c++)
                #pragma unroll
                for (int d = 0; d < 4; d++) acc[a][b][c][d] = 0.f;

    const __nv_bfloat16 *ah = init ? (g_wh + OFF_OBS0) : g_omh;
    const __nv_bfloat16 *al = init ? (g_wl + OFF_OBS0) : g_oml;
    const __nv_bfloat16 *acth = g_wh + OFF_ACT + (size_t)t * BATCH * ACT_D;
    const __nv_bfloat16 *actl = g_wl + OFF_ACT + (size_t)t * BATCH * ACT_D;

    #define D_LOADA(cc, bb) do { \
        if ((cc) < 8) { \
            cpa_bf<128>(sm + (bb) * 5120, ah, OBS_D, m0, (cc) << 5); \
            cpa_bf<128>(sm + (bb) * 5120 + 2560, al, OBS_D, m0, (cc) << 5); \
        } else if (!init) { \
            cpa_bf<128>(sm + (bb) * 5120, acth, ACT_D, m0, 0); \
            cpa_bf<128>(sm + (bb) * 5120 + 2560, actl, ACT_D, m0, 0); \
        } else { \
            float4 z4 = make_float4(0.f, 0.f, 0.f, 0.f); \
            _Pragma("unroll") \
            for (int i = 0; i < 5; i++) { \
                int p = tid + i * NTHR; \
                if (p < 1280) *(float4 *)(sm + (bb) * 5120 + p * 4) = z4; } \
        } } while (0)
    #define D_LOADW(cc, bb) do { \
        _Pragma("unroll") \
        for (int gg = 0; gg < 3; gg++) { \
            int bse = 10240 + (bb) * 7680 + gg * 2560; \
            cpa_bf<64>(sm + bse, g_wh + OFF_WIH, 288, gg * HID + j0, (cc) << 5); \
            cpa_bf<64>(sm + bse + 1280, g_wl + OFF_WIH, 288, gg * HID + j0, (cc) << 5); \
        } } while (0)

    D_LOADA(0, 0); D_LOADW(0, 0); CP_COMMIT;
    for (int c = 0; c < 9; c++) {
        int buf = c & 1;
        if (c < 8) { D_LOADA(c + 1, buf ^ 1); D_LOADW(c + 1, buf ^ 1); CP_COMMIT; CP_WAIT1; }
        else CP_WAIT0;
        __syncthreads();
        const uint32_t *sA = (const uint32_t *)(sm + buf * 5120);
        const uint32_t *sW = (const uint32_t *)(sm + 10240 + buf * 7680);
        #pragma unroll
        for (int s = 0; s < 2; s++) {
            int w0 = 8 * s + t4, w1 = w0 + 4;
            uint32_t aH[2][4], aL[2][4];
            #pragma unroll
            for (int mt = 0; mt < 2; mt++) {
                int r = (wm * 32 + mt * 16 + g) * 20;
                aH[mt][0] = sA[r + w0]; aH[mt][1] = sA[r + 160 + w0];
                aH[mt][2] = sA[r + w1]; aH[mt][3] = sA[r + 160 + w1];
                aL[mt][0] = sA[2560 + r + w0]; aL[mt][1] = sA[2560 + r + 160 + w0];
                aL[mt][2] = sA[2560 + r + w1]; aL[mt][3] = sA[2560 + r + 160 + w1];
            }
            #pragma unroll
            for (int gg = 0; gg < 3; gg++) {
                // gate stride 2560 u32 (H 1280 + L 1280); L plane at +1280 u32
                const uint32_t *wg = sW + gg * 2560;
                #pragma unroll
                for (int nt = 0; nt < 4; nt++) {
                    int rb = (wn * 32 + nt * 8 + g) * 20;
                    uint32_t bH0 = wg[rb + w0], bH1 = wg[rb + w1];
                    uint32_t bL0 = wg[1280 + rb + w0], bL1 = wg[1280 + rb + w1];
                    #pragma unroll
                    for (int mt = 0; mt < 2; mt++) {
                        mmabf(acc[gg][mt][nt], aH[mt], bH0, bH1);
                        mmabf(acc[gg][mt][nt], aH[mt], bL0, bL1);
                        mmabf(acc[gg][mt][nt], aL[mt], bH0, bH1);
                    }
                }
            }
        }
        __syncthreads();
    }
    #undef D_LOADA
    #undef D_LOADW

    // fused GRU pointwise
    #pragma unroll
    for (int mt = 0; mt < 2; mt++) {
        int r0 = m0 + wm * 32 + mt * 16 + g;
        #pragma unroll
        for (int half = 0; half < 2; half++) {
            int b = r0 + half * 8, ci = half * 2;
            #pragma unroll
            for (int nt = 0; nt < 4; nt++) {
                int j = j0 + wn * 32 + nt * 8 + 2 * t4;
                float2 bir = *(const float2 *)(P.bih + j);
                float2 biz = *(const float2 *)(P.bih + HID + j);
                float2 bin = *(const float2 *)(P.bih + 2 * HID + j);
                float2 ghr, ghz, ghn, hp;
                if (init) {
                    ghr = *(const float2 *)(P.bhh + j);
                    ghz = *(const float2 *)(P.bhh + HID + j);
                    ghn = *(const float2 *)(P.bhh + 2 * HID + j);
                    hp = make_float2(0.f, 0.f);
                } else {
                    const float *gb = g_gh + (size_t)b * GATES + j;
                    ghr = __ldcg((const float2 *)gb);
                    ghz = __ldcg((const float2 *)(gb + HID));
                    ghn = __ldcg((const float2 *)(gb + 2 * HID));
                    uint32_t hh = __ldcg((const uint32_t *)(hhR + (size_t)b * HID + j));
                    uint32_t hl = __ldcg((const uint32_t *)(hlR + (size_t)b * HID + j));
                    __nv_bfloat162 hh2 = *(__nv_bfloat162 *)&hh, hl2 = *(__nv_bfloat162 *)&hl;
                    hp = make_float2(bf2f(hh2.x) + bf2f(hl2.x), bf2f(hh2.y) + bf2f(hl2.y));
                }
                float ox, oy;
                {
                    float rg = sigf(acc[0][mt][nt][ci] + bir.x + ghr.x);
                    float zg = sigf(acc[1][mt][nt][ci] + biz.x + ghz.x);
                    float ng = tanhfast(acc[2][mt][nt][ci] + bin.x + rg * ghn.x);
                    ox = (1.f - zg) * ng + zg * hp.x;
                }
                {
                    float rg = sigf(acc[0][mt][nt][ci + 1] + bir.y + ghr.y);
                    float zg = sigf(acc[1][mt][nt][ci + 1] + biz.y + ghz.y);
                    float ng = tanhfast(acc[2][mt][nt][ci + 1] + bin.y + rg * ghn.y);
                    oy = (1.f - zg) * ng + zg * hp.y;
                }
                __nv_bfloat162 l2, h2 = split2(ox, oy, l2);
                *(__nv_bfloat162 *)(hhW + (size_t)b * HID + j) = h2;
                *(__nv_bfloat162 *)(hlW + (size_t)b * HID + j) = l2;
            }
        }
    }
}

__device__ void conv_all(const Params &P) {
    const float *srcs[9] = {P.whh, P.wih, P.ow0, P.ow1, P.ow2, P.rw0, P.rw1, P.obs, P.act};
    const int ns[9] = {3145728, 884736, 524288, 262144, 131072, 524288, 262144, 131072, 1048576};
    const int offs[9] = {OFF_WHH, OFF_WIH, OFF_OW0, OFF_OW1, OFF_OW2, OFF_RW0, OFF_RW1, OFF_OBS0, OFF_ACT};
    for (int rgn = 0; rgn < 9; rgn++) {
        const float *src = srcs[rgn];
        int n = ns[rgn];
        __nv_bfloat16 *hi = g_wh + offs[rgn], *lo = g_wl + offs[rgn];
        for (int i = (blockIdx.x * NTHR + threadIdx.x) * 4; i < n; i += NBLK * NTHR * 4) {
            float4 v = __ldg((const float4 *)(src + i));
            __nv_bfloat162 l0, l1;
            __nv_bfloat162 h0 = split2(v.x, v.y, l0);
            __nv_bfloat162 h1 = split2(v.z, v.w, l1);
            *(__nv_bfloat162 *)(hi + i) = h0; *(__nv_bfloat162 *)(hi + i + 2) = h1;
            *(__nv_bfloat162 *)(lo + i) = l0; *(__nv_bfloat162 *)(lo + i + 2) = l1;
        }
    }
}

__global__ void __launch_bounds__(NTHR, 1) wm_kernel(Params P) {
    extern __shared__ float sm[];
    __shared__ float red[16];
    const int tid = threadIdx.x, wid = tid >> 5, lid = tid & 31, bid = blockIdx.x;
    const int lane = tid & 31, g = lane >> 2, t4 = lane & 3;
    const int wm4 = wid >> 2, wn4 = wid & 3;

    unsigned phase = *(volatile unsigned *)&g_gen;
    if (bid == 0 && tid == 0) { g_sse[0] = 0.f; g_sse[1] = 0.f; }
    float lpo = 0.f, lpr = 0.f;

    conv_all(P);
    grid_sync(phase);

    // h0 = GRU([obs0, 0], 0)
    if (bid < 64) stageD(P, 0, true, nullptr, nullptr, g_hh[0], g_hl[0], sm);
    grid_sync(phase);

    for (int t = 0; t < T_STEPS; t++) {
        const __nv_bfloat16 *hhR = g_hh[t & 1], *hlR = g_hl[t & 1];

        // A: gh = h@Whh^T + bhh ; o1/r1 = elu(h@W0^T + b0). 128 tiles, K=1024.
        if (bid < 128) {
            int nt = bid & 31, m0 = (bid >> 5) << 7;
            float acc[4][4][4];
            #pragma unroll
            for (int i = 0; i < 4; i++)
                #pragma unroll
                for (int j = 0; j < 4; j++)
                    #pragma unroll
                    for (int k = 0; k < 4; k++) acc[i][j][k] = 0.f;
            if (nt < 24) {
                int n0 = nt << 7;
                mm_gemm(acc, hhR, hlR, HID, g_wh + OFF_WHH, g_wl + OFF_WHH, HID, m0, n0, HID, sm);
                epi44_f32(acc, P.bhh, g_gh, GATES, m0, n0);
            } else if (nt < 28) {
                int n0 = (nt - 24) << 7;
                mm_gemm(acc, hhR, hlR, HID, g_wh + OFF_OW0, g_wl + OFF_OW0, HID, m0, n0, HID, sm);
                epi44_bf(acc, P.ob0, g_o1h, g_o1l, FEAT, m0, n0);
            } else {
                int n0 = (nt - 28) << 7;
                mm_gemm(acc, hhR, hlR, HID, g_wh + OFF_RW0, g_wl + OFF_RW0, HID, m0, n0, HID, sm);
                epi44_bf(acc, P.rb0, g_r1h, g_r1l, FEAT, m0, n0);
            }
        }
        grid_sync(phase);

        // B: o2/r2 = elu(x@W1^T + b1). 32 tiles, K=512.
        if (bid < 32) {
            int idx = bid & 15, m0 = (idx >> 2) << 7, n0 = (idx & 3) << 7;
            float acc[4][4][4];
            #pragma unroll
            for (int i = 0; i < 4; i++)
                #pragma unroll
                for (int j = 0; j < 4; j++)
                    #pragma unroll
                    for (int k = 0; k < 4; k++) acc[i][j][k] = 0.f;
            if (bid < 16) {
                mm_gemm(acc, g_o1h, g_o1l, FEAT, g_wh + OFF_OW1, g_wl + OFF_OW1, FEAT, m0, n0, FEAT, sm);
                epi44_bf(acc, P.ob1, g_o2h, g_o2l, FEAT, m0, n0);
            } else {
                mm_gemm(acc, g_r1h, g_r1l, FEAT, g_wh + OFF_RW1, g_wl + OFF_RW1, FEAT, m0, n0, FEAT, sm);
                epi44_bf(acc, P.rb1, g_r2h, g_r2l, FEAT, m0, n0);
            }
        }
        grid_sync(phase);

        // C: obs head (8 tiles, K=512) + rew GEMV (8 CTAs).
        if (bid < 8) {
            int m0 = (bid >> 1) << 7, n0 = (bid & 1) << 7;
            float acc[4][4][4];
            #pragma unroll
            for (int i = 0; i < 4; i++)
                #pragma unroll
                for (int j = 0; j < 4; j++)
                    #pragma unroll
                    for (int k = 0; k < 4; k++) acc[i][j][k] = 0.f;
            mm_gemm(acc, g_o2h, g_o2l, FEAT, g_wh + OFF_OW2, g_wl + OFF_OW2, FEAT, m0, n0, FEAT, sm);
            #pragma unroll
            for (int mt = 0; mt < 4; mt++) {
                int r0 = m0 + wm4 * 64 + mt * 16 + g;
                #pragma unroll
                for (int nt = 0; nt < 4; nt++) {
                    int col = n0 + wn4 * 32 + nt * 8 + 2 * t4;
                    float2 bb = *(const float2 *)(P.ob2 + col);
                    #pragma unroll
                    for (int half = 0; half < 2; half++) {
                        int r = r0 + half * 8, ci = half * 2;
                        float m0v = acc[mt][nt][ci] + bb.x;
                        float m1v = acc[mt][nt][ci + 1] + bb.y;
                        size_t off = (size_t)t * BATCH * OBS_D + (size_t)r * OBS_D + col;
                        __nv_bfloat162 l2, h2 = split2(m0v, m1v, l2);
                        *(__nv_bfloat162 *)(g_omh + (size_t)r * OBS_D + col) = h2;
                        *(__nv_bfloat162 *)(g_oml + (size_t)r * OBS_D + col) = l2;
                        P.out[1 + off] = m0v;
                        P.out[1 + off + 1] = m1v;
                        float2 ob = *(const float2 *)(P.obs + off);
                        float dx = ob.x - m0v, dy = ob.y - m1v;
                        lpo += dx * dx + dy * dy;
                    }
                }
            }
        } else if (bid < 16) {
            int b = ((bid - 8) << 6) + (tid >> 2), seg = tid & 3;
            const uint32_t *rh = (const uint32_t *)(g_r2h + (size_t)b * FEAT + seg * 128);
            const uint32_t *rl = (const uint32_t *)(g_r2l + (size_t)b * FEAT + seg * 128);
            const float2 *w2 = (const float2 *)(P.rw2 + seg * 128);
            float s = 0.f;
            #pragma unroll
            for (int k = 0; k < 64; k++) {
                uint32_t hu = __ldcg(rh + k), lu = __ldcg(rl + k);
                __nv_bfloat162 h2 = *(__nv_bfloat162 *)&hu, l2 = *(__nv_bfloat162 *)&lu;
                float2 wv = __ldg(w2 + k);
                s += (bf2f(h2.x) + bf2f(l2.x)) * wv.x + (bf2f(h2.y) + bf2f(l2.y)) * wv.y;
            }
            s += __shfl_xor_sync(0xffffffffu, s, 1);
            s += __shfl_xor_sync(0xffffffffu, s, 2);
            if (seg == 0) {
                float mean = s + __ldg(P.rb2);
                P.out[1 + (size_t)T_STEPS * BATCH * OBS_D + (size_t)t * BATCH + b] = mean;
                float d = __ldg(P.rew + (size_t)t * BATCH + b) - mean;
                lpr += d * d;
            }
        }
        grid_sync(phase);

        // D: gi (3 gates) + fused GRU pointwise. 64 tiles.
        if (bid < 64)
            stageD(P, t, false, hhR, hlR, g_hh[(t + 1) & 1], g_hl[(t + 1) & 1], sm);
        grid_sync(phase);
    }

    // loss reduction
    #pragma unroll
    for (int o = 16; o; o >>= 1) {
        lpo += __shfl_xor_sync(0xffffffffu, lpo, o);
        lpr += __shfl_xor_sync(0xffffffffu, lpr, o);
    }
    __syncthreads();
    if (lid == 0) { red[wid] = lpo; red[8 + wid] = lpr; }
    __syncthreads();
    if (tid == 0) {
        float a = 0.f, b = 0.f;
        for (int w = 0; w < 8; w++) { a += red[w]; b += red[8 + w]; }
        atomicAdd(&g_sse[0], a);
        atomicAdd(&g_sse[1], b);
    }
    grid_sync(phase);
    if (bid == 0 && tid == 0) {
        float inv = 1.f / (float)(T_STEPS * BATCH);
        P.out[0] = 0.5f * (g_sse[0] + g_sse[1]) * inv + 0.5f * (OBS_D + 1) * LOG2PI;
    }
}

extern "C" void kernel_launch(void* const* d_in, const int* in_sizes, int n_in,
                              void* d_out, int out_size) {
    Params P;
    P.obs = (const float *)d_in[0];
    P.act = (const float *)d_in[1];
    P.rew = (const float *)d_in[2];
    P.wih = (const float *)d_in[3];
    P.whh = (const float *)d_in[4];
    P.bih = (const float *)d_in[5];
    P.bhh = (const float *)d_in[6];
    P.ow0 = (const float *)d_in[7];
    P.ob0 = (const float *)d_in[8];
    P.ow1 = (const float *)d_in[9];
    P.ob1 = (const float *)d_in[10];
    P.ow2 = (const float *)d_in[11];
    P.ob2 = (const float *)d_in[12];
    P.rw0 = (const float *)d_in[13];
    P.rb0 = (const float *)d_in[14];
    P.rw1 = (const float *)d_in[15];
    P.rb1 = (const float *)d_in[16];
    P.rw2 = (const float *)d_in[17];
    P.rb2 = (const float *)d_in[18];
    P.out = (float *)d_out;
    cudaFuncSetAttribute(wm_kernel, cudaFuncAttributeMaxDynamicSharedMemorySize, SMEM_DYN);
    wm_kernel<<<NBLK, NTHR, SMEM_DYN>>>(P);
}